// round 1
// baseline (speedup 1.0000x reference)
#include <cuda_runtime.h>
#include <cstdint>
#include <math.h>

#define BATCH 8192
#define HID   1024

// Scratch (allocation-free: __device__ globals)
__device__ float g_c  [(size_t)BATCH * HID];   // c_t -> softmax a_t (in place)
__device__ float g_php[(size_t)BATCH * HID];   // relu(combined @ What.T + bhat)
__device__ float g_rh [(size_t)BATCH * HID];   // sigmoid(r_pre) * hidden
__device__ float g_z  [(size_t)BATCH * HID];   // sigmoid(z_pre)
__device__ float g_u  [(size_t)BATCH * HID];   // x @ Wxh.T + bias_h

#define BM 128
#define BN 128
#define BK 16
#define SK 20   // BK + 4 pad -> conflict-free fragment loads

__device__ __forceinline__ uint32_t f2tf32(float f) {
    uint32_t u;
    asm("cvt.rna.tf32.f32 %0, %1;" : "=r"(u) : "f"(f));
    return u;
}

enum { M_NONE = 0, M_RELU = 1, M_SIG = 2, M_SIGMUL = 3, M_FINAL = 4 };

__device__ __forceinline__ float epi(int mode, float v, size_t idx,
                                     const float* __restrict__ hidden) {
    switch (mode) {
        case M_NONE:   return v;
        case M_RELU:   return fmaxf(v, 0.f);
        case M_SIG:    return 1.f / (1.f + __expf(-v));
        case M_SIGMUL: return (1.f / (1.f + __expf(-v))) * hidden[idx];
        default: {  // M_FINAL: v = (r*h) @ Whh.T partial
            float ht = tanhf(g_u[idx] + v);
            float z  = g_z[idx];
            return (1.f - z) * ht + z * hidden[idx] + g_c[idx] * g_php[idx];
        }
    }
}

// C[B, N] = f(A1 @ W1.T + A2 @ W2.T + bias), tf32 mma, fp32 accum.
// A rows stride 1024. W rows stride ld1/ld2 (handles weight_c [:, :1024]/[:, 1024:]).
__global__ __launch_bounds__(256)
void gemm_tf32_kernel(const float* __restrict__ A1p, const float* __restrict__ W1, int ld1,
                      const float* __restrict__ A2,  const float* __restrict__ W2, int ld2,
                      const float* __restrict__ bias,
                      const float* __restrict__ hidden,
                      float* __restrict__ outp,
                      int mode, int out_sel, int a1_is_rh)
{
    __shared__ uint32_t As[BM][SK];
    __shared__ uint32_t Ws[BN][SK];

    const int tid  = threadIdx.x;
    const int warp = tid >> 5, lane = tid & 31;
    const int g = lane >> 2, tig = lane & 3;
    const int wm = warp >> 1, wn = warp & 1;   // 4x2 warp grid, warp tile 32x64

    const int bm = blockIdx.y * BM;
    const int bn = blockIdx.x * BN;

    float acc[2][8][4];
#pragma unroll
    for (int i = 0; i < 2; i++)
#pragma unroll
        for (int j = 0; j < 8; j++)
#pragma unroll
            for (int q = 0; q < 4; q++) acc[i][j][q] = 0.f;

    const float* A1 = a1_is_rh ? g_rh : A1p;

#pragma unroll 1
    for (int phase = 0; phase < 2; phase++) {
        const float* A = phase ? A2 : A1;
        const float* W = phase ? W2 : W1;
        const int    ld = phase ? ld2 : ld1;
        if (A == nullptr) continue;

#pragma unroll 1
        for (int k0 = 0; k0 < 1024; k0 += BK) {
            // Load A tile (128x16) and W tile (128x16), convert to tf32.
#pragma unroll
            for (int r = 0; r < 2; r++) {
                int idx = r * 256 + tid;        // 512 float4s
                int row = idx >> 2;
                int cg  = idx & 3;
                float4 a4 = *reinterpret_cast<const float4*>(
                    &A[(size_t)(bm + row) * 1024 + k0 + cg * 4]);
                uint4 u4 = make_uint4(f2tf32(a4.x), f2tf32(a4.y), f2tf32(a4.z), f2tf32(a4.w));
                *reinterpret_cast<uint4*>(&As[row][cg * 4]) = u4;

                float4 w4 = *reinterpret_cast<const float4*>(
                    &W[(size_t)(bn + row) * ld + k0 + cg * 4]);
                uint4 v4 = make_uint4(f2tf32(w4.x), f2tf32(w4.y), f2tf32(w4.z), f2tf32(w4.w));
                *reinterpret_cast<uint4*>(&Ws[row][cg * 4]) = v4;
            }
            __syncthreads();

#pragma unroll
            for (int kk = 0; kk < 2; kk++) {
                uint32_t af[2][4];
#pragma unroll
                for (int i = 0; i < 2; i++) {
                    int r0 = wm * 32 + i * 16 + g;
                    af[i][0] = As[r0    ][kk * 8 + tig    ];
                    af[i][1] = As[r0 + 8][kk * 8 + tig    ];
                    af[i][2] = As[r0    ][kk * 8 + tig + 4];
                    af[i][3] = As[r0 + 8][kk * 8 + tig + 4];
                }
                uint32_t bf[8][2];
#pragma unroll
                for (int j = 0; j < 8; j++) {
                    int n0 = wn * 64 + j * 8 + g;
                    bf[j][0] = Ws[n0][kk * 8 + tig    ];
                    bf[j][1] = Ws[n0][kk * 8 + tig + 4];
                }
#pragma unroll
                for (int i = 0; i < 2; i++)
#pragma unroll
                    for (int j = 0; j < 8; j++) {
                        asm volatile(
                            "mma.sync.aligned.m16n8k8.row.col.f32.tf32.tf32.f32 "
                            "{%0,%1,%2,%3},{%4,%5,%6,%7},{%8,%9},{%0,%1,%2,%3};\n"
                            : "+f"(acc[i][j][0]), "+f"(acc[i][j][1]),
                              "+f"(acc[i][j][2]), "+f"(acc[i][j][3])
                            : "r"(af[i][0]), "r"(af[i][1]), "r"(af[i][2]), "r"(af[i][3]),
                              "r"(bf[j][0]), "r"(bf[j][1]));
                    }
            }
            __syncthreads();
        }
    }

    float* out;
    switch (out_sel) {
        case 0: out = g_c;   break;
        case 1: out = g_php; break;
        case 2: out = g_rh;  break;
        case 3: out = g_z;   break;
        case 4: out = g_u;   break;
        default: out = outp; break;
    }

#pragma unroll
    for (int i = 0; i < 2; i++) {
#pragma unroll
        for (int j = 0; j < 8; j++) {
            int rowA = bm + wm * 32 + i * 16 + g;
            int colA = bn + wn * 64 + j * 8 + 2 * tig;
            float b0 = bias ? bias[colA]     : 0.f;
            float b1 = bias ? bias[colA + 1] : 0.f;
            size_t i00 = (size_t)rowA * HID + colA;
            size_t i10 = i00 + (size_t)8 * HID;
            out[i00    ] = epi(mode, acc[i][j][0] + b0, i00,     hidden);
            out[i00 + 1] = epi(mode, acc[i][j][1] + b1, i00 + 1, hidden);
            out[i10    ] = epi(mode, acc[i][j][2] + b0, i10,     hidden);
            out[i10 + 1] = epi(mode, acc[i][j][3] + b1, i10 + 1, hidden);
        }
    }
}

// Row softmax over g_c in place: 1 block = 1 row, 256 threads x 4 elems.
__global__ __launch_bounds__(256)
void softmax_kernel()
{
    const int row = blockIdx.x;
    float* p = g_c + (size_t)row * HID;
    const int tid = threadIdx.x;

    float4 v = reinterpret_cast<float4*>(p)[tid];
    float m = fmaxf(fmaxf(v.x, v.y), fmaxf(v.z, v.w));
#pragma unroll
    for (int o = 16; o; o >>= 1) m = fmaxf(m, __shfl_xor_sync(~0u, m, o));

    __shared__ float smax[8];
    __shared__ float ssum[8];
    if ((tid & 31) == 0) smax[tid >> 5] = m;
    __syncthreads();
    float M = -1e30f;
#pragma unroll
    for (int i = 0; i < 8; i++) M = fmaxf(M, smax[i]);

    float e0 = expf(v.x - M), e1 = expf(v.y - M), e2 = expf(v.z - M), e3 = expf(v.w - M);
    float s = e0 + e1 + e2 + e3;
#pragma unroll
    for (int o = 16; o; o >>= 1) s += __shfl_xor_sync(~0u, s, o);
    if ((tid & 31) == 0) ssum[tid >> 5] = s;
    __syncthreads();
    float S = 0.f;
#pragma unroll
    for (int i = 0; i < 8; i++) S += ssum[i];
    float inv = 1.f / S;

    reinterpret_cast<float4*>(p)[tid] = make_float4(e0 * inv, e1 * inv, e2 * inv, e3 * inv);
}

extern "C" void kernel_launch(void* const* d_in, const int* in_sizes, int n_in,
                              void* d_out, int out_size)
{
    const float* x    = (const float*)d_in[0];
    const float* h    = (const float*)d_in[1];
    const float* wxr  = (const float*)d_in[2];
    const float* whr  = (const float*)d_in[3];
    const float* br   = (const float*)d_in[4];
    const float* wxz  = (const float*)d_in[5];
    const float* whz  = (const float*)d_in[6];
    const float* bz   = (const float*)d_in[7];
    const float* wxh  = (const float*)d_in[8];
    const float* whh  = (const float*)d_in[9];
    const float* bh   = (const float*)d_in[10];
    const float* wc   = (const float*)d_in[11];
    const float* bc   = (const float*)d_in[12];
    const float* what = (const float*)d_in[13];
    const float* bhat = (const float*)d_in[14];
    float* out = (float*)d_out;

    dim3 grid(HID / BN, BATCH / BM);
    dim3 block(256);

    // c_t = [x,h] @ Wc.T + bc          (Wc is [1024, 2048]: x-half ld 2048, h-half offset +1024)
    gemm_tf32_kernel<<<grid, block>>>(x, wc, 2048, h, wc + 1024, 2048, bc, nullptr, nullptr, M_NONE, 0, 0);
    // relu([x,h] @ What.T + bhat)
    gemm_tf32_kernel<<<grid, block>>>(x, what, 2048, h, what + 1024, 2048, bhat, nullptr, nullptr, M_RELU, 1, 0);
    // r*h = sigmoid(x@Wxr.T + h@Whr.T + br) * h
    gemm_tf32_kernel<<<grid, block>>>(x, wxr, 1024, h, whr, 1024, br, h, nullptr, M_SIGMUL, 2, 0);
    // z = sigmoid(x@Wxz.T + h@Whz.T + bz)
    gemm_tf32_kernel<<<grid, block>>>(x, wxz, 1024, h, whz, 1024, bz, nullptr, nullptr, M_SIG, 3, 0);
    // u = x@Wxh.T + bh
    gemm_tf32_kernel<<<grid, block>>>(x, wxh, 1024, nullptr, nullptr, 0, bh, nullptr, nullptr, M_NONE, 4, 0);
    // a = softmax(c) in place
    softmax_kernel<<<BATCH, 256>>>();
    // h_t = (1-z)*tanh(u + (r*h)@Whh.T) + z*h + a*php
    gemm_tf32_kernel<<<grid, block>>>(nullptr, whh, 1024, nullptr, nullptr, 0, nullptr, h, out, M_FINAL, 5, 1);
}

// round 3
// speedup vs baseline: 1.8036x; 1.8036x over previous
#include <cuda_runtime.h>
#include <cstdint>
#include <math.h>

#define BATCH 8192
#define HID   1024

// ---------------- scratch (allocation-free: __device__ globals) ----------------
__device__ float g_c  [(size_t)BATCH * HID];   // c_t -> softmax a_t (in place)
__device__ float g_php[(size_t)BATCH * HID];   // relu(combined @ What.T + bhat)
__device__ float g_rh [(size_t)BATCH * HID];   // round_tf32(sigmoid(r_pre) * hidden)
__device__ float g_z  [(size_t)BATCH * HID];   // sigmoid(z_pre)
__device__ float g_u  [(size_t)BATCH * HID];   // x @ Wxh.T + bias_h

// pre-rounded (tf32-rna) operands, packed into one buffer (element offsets)
#define PX    0
#define PH    8388608
#define PWC   16777216
#define PWHAT 18874368
#define PWXR  20971520
#define PWHR  22020096
#define PWXZ  23068672
#define PWHZ  24117248
#define PWXH  25165824
#define PWHH  26214400
#define PTOT  27262976
__device__ float g_pre[PTOT];

__device__ __forceinline__ float rna_tf32(float f) {
    uint32_t u;
    asm("cvt.rna.tf32.f32 %0, %1;" : "=r"(u) : "f"(f));
    return __uint_as_float(u);
}
__device__ __forceinline__ uint32_t smem_to_u32(const void* p) {
    uint32_t a;
    asm("{ .reg .u64 tmp; cvta.to.shared.u64 tmp, %1; cvt.u32.u64 %0, tmp; }"
        : "=r"(a) : "l"(p));
    return a;
}

// ---------------- geometry ----------------
#define BM 128
#define BN 256
#define BK 16
#define SK 20                       // 16 + 4 pad words -> conflict-free fragment LDS
#define A_ST_B  10240               // 128*20*4 bytes per A stage
#define B_ST_B  20480               // 256*20*4 bytes per B stage
#define OFF_B_B 40960               // 4 A stages
#define SMEM_BYTES (OFF_B_B + 4 * B_ST_B)   // 122880

enum { M_NONE = 0, M_RELU = 1, M_SIG = 2, M_SIGMUL = 3, M_FINAL = 4 };

struct GateCfg {
    const float* A1; const float* W1;
    const float* A2; const float* W2;
    const float* bias; float* out;
    int ld1, ld2, n1, n2, mode;      // n1/n2 = #K16 chunks per phase
};
struct KParams { GateCfg g[6]; const float* hidden; };

// ---------------- pre-rounding pass (fp32 -> tf32-rna) ----------------
__global__ __launch_bounds__(256)
void preround_kernel(const float* x, const float* h, const float* wc, const float* what,
                     const float* wxr, const float* whr, const float* wxz, const float* whz,
                     const float* wxh, const float* whh)
{
    const int tid = blockIdx.x * blockDim.x + threadIdx.x;
    const int nt  = gridDim.x * blockDim.x;
    const float* srcs[10] = {x, h, wc, what, wxr, whr, wxz, whz, wxh, whh};
    float* dsts[10] = {g_pre + PX, g_pre + PH, g_pre + PWC, g_pre + PWHAT, g_pre + PWXR,
                       g_pre + PWHR, g_pre + PWXZ, g_pre + PWHZ, g_pre + PWXH, g_pre + PWHH};
    const int n4s[10] = {2097152, 2097152, 524288, 524288, 262144,
                         262144, 262144, 262144, 262144, 262144};
#pragma unroll 1
    for (int s = 0; s < 10; s++) {
        const float4* sp = (const float4*)srcs[s];
        float4*       dp = (float4*)dsts[s];
        const int n4 = n4s[s];
        for (int i = tid; i < n4; i += nt) {
            float4 v = sp[i];
            dp[i] = make_float4(rna_tf32(v.x), rna_tf32(v.y), rna_tf32(v.z), rna_tf32(v.w));
        }
    }
}

// ---------------- tf32 mma.sync GEMM, 128x256 CTA, 64x64 warp, 4-stage cp.async ----------------
__global__ __launch_bounds__(256, 1)
void rau_gemm(KParams P, int gbase)
{
    extern __shared__ float smem[];
    const uint32_t su = smem_to_u32(smem);

    const GateCfg cfg = P.g[gbase + blockIdx.z];

    const int t = threadIdx.x;
    const int w = t >> 5, lane = t & 31;
    const int g = lane >> 2, tig = lane & 3;
    const int wm = w >> 2, wn = w & 3;        // 2x4 warp grid, 64x64 warp tile
    const int bm = blockIdx.y * BM;
    const int bn = blockIdx.x * BN;
    const int n1 = cfg.n1;
    const int n  = n1 + cfg.n2;

    // Per-thread load slots: 2 x 16B A, 4 x 16B B per chunk (32-bit offsets).
    uint32_t baseA[2], offA[2];
    uint32_t baseB[4], oW1[4], oW2[4];
#pragma unroll
    for (int j = 0; j < 2; j++) {
        int idx = j * 256 + t, row = idx >> 2, cg = idx & 3;
        baseA[j] = (uint32_t)(row * 80 + cg * 16);
        offA[j]  = (uint32_t)((bm + row) * HID + cg * 4);
    }
#pragma unroll
    for (int j = 0; j < 4; j++) {
        int idx = j * 256 + t, row = idx >> 2, cg = idx & 3;
        baseB[j] = (uint32_t)(OFF_B_B + row * 80 + cg * 16);
        oW1[j]   = (uint32_t)((bn + row) * cfg.ld1 + cg * 4);
        oW2[j]   = (uint32_t)((bn + row) * cfg.ld2 + cg * 4);
    }

    auto load_chunk = [&](int c, int st) {
        const bool p1 = (c < n1);
        const uint32_t kof = (uint32_t)(p1 ? c : c - n1) * 16u;
        const float* Ap = p1 ? cfg.A1 : cfg.A2;
        const float* Wp = p1 ? cfg.W1 : cfg.W2;
#pragma unroll
        for (int j = 0; j < 2; j++) {
            const float* s = Ap + offA[j] + kof;
            asm volatile("cp.async.cg.shared.global [%0], [%1], 16;\n"
                         :: "r"(su + st * A_ST_B + baseA[j]), "l"(s));
        }
#pragma unroll
        for (int j = 0; j < 4; j++) {
            const float* s = Wp + (p1 ? oW1[j] : oW2[j]) + kof;
            asm volatile("cp.async.cg.shared.global [%0], [%1], 16;\n"
                         :: "r"(su + st * B_ST_B + baseB[j]), "l"(s));
        }
    };

    float acc[4][8][4];
#pragma unroll
    for (int i = 0; i < 4; i++)
#pragma unroll
        for (int j = 0; j < 8; j++)
#pragma unroll
            for (int q = 0; q < 4; q++) acc[i][j][q] = 0.f;

    load_chunk(0, 0);
    asm volatile("cp.async.commit_group;\n" ::: "memory");
    load_chunk(1, 1);
    asm volatile("cp.async.commit_group;\n" ::: "memory");

#pragma unroll 1
    for (int i = 0; i < n; i++) {
        asm volatile("cp.async.wait_group 1;\n" ::: "memory");
        __syncthreads();
        if (i + 2 < n) load_chunk(i + 2, (i + 2) & 3);
        asm volatile("cp.async.commit_group;\n" ::: "memory");

        const int st = i & 3;
        const uint32_t* Asu = (const uint32_t*)((const char*)smem + st * A_ST_B);
        const uint32_t* Bsu = (const uint32_t*)((const char*)smem + OFF_B_B + st * B_ST_B);

#pragma unroll
        for (int kk = 0; kk < 2; kk++) {
            uint32_t af[4][4];
#pragma unroll
            for (int ii = 0; ii < 4; ii++) {
                int r0 = wm * 64 + ii * 16 + g;
                af[ii][0] = Asu[ r0      * SK + kk * 8 + tig    ];
                af[ii][1] = Asu[(r0 + 8) * SK + kk * 8 + tig    ];
                af[ii][2] = Asu[ r0      * SK + kk * 8 + tig + 4];
                af[ii][3] = Asu[(r0 + 8) * SK + kk * 8 + tig + 4];
            }
            uint32_t bf[8][2];
#pragma unroll
            for (int jj = 0; jj < 8; jj++) {
                int n0 = wn * 64 + jj * 8 + g;
                bf[jj][0] = Bsu[n0 * SK + kk * 8 + tig    ];
                bf[jj][1] = Bsu[n0 * SK + kk * 8 + tig + 4];
            }
#pragma unroll
            for (int ii = 0; ii < 4; ii++)
#pragma unroll
                for (int jj = 0; jj < 8; jj++) {
                    asm volatile(
                        "mma.sync.aligned.m16n8k8.row.col.f32.tf32.tf32.f32 "
                        "{%0,%1,%2,%3},{%4,%5,%6,%7},{%8,%9},{%0,%1,%2,%3};\n"
                        : "+f"(acc[ii][jj][0]), "+f"(acc[ii][jj][1]),
                          "+f"(acc[ii][jj][2]), "+f"(acc[ii][jj][3])
                        : "r"(af[ii][0]), "r"(af[ii][1]), "r"(af[ii][2]), "r"(af[ii][3]),
                          "r"(bf[jj][0]), "r"(bf[jj][1]));
                }
        }
    }

    // ---------------- fused epilogue ----------------
    const int mode = cfg.mode;
    float* out = cfg.out;
    const float* bias = cfg.bias;
    const float* hid = P.hidden;

#pragma unroll
    for (int ii = 0; ii < 4; ii++) {
#pragma unroll
        for (int jj = 0; jj < 8; jj++) {
            const int r0  = bm + wm * 64 + ii * 16 + g;
            const int col = bn + wn * 64 + jj * 8 + 2 * tig;
            float b0 = 0.f, b1 = 0.f;
            if (bias) { b0 = bias[col]; b1 = bias[col + 1]; }
#pragma unroll
            for (int hrow = 0; hrow < 2; hrow++) {
                const size_t idx = (size_t)(r0 + hrow * 8) * HID + col;
                float v0 = acc[ii][jj][hrow * 2    ] + b0;
                float v1 = acc[ii][jj][hrow * 2 + 1] + b1;
                float2 res;
                if (mode == M_NONE) {
                    res = make_float2(v0, v1);
                } else if (mode == M_RELU) {
                    res = make_float2(fmaxf(v0, 0.f), fmaxf(v1, 0.f));
                } else if (mode == M_SIG) {
                    res = make_float2(1.f / (1.f + __expf(-v0)),
                                      1.f / (1.f + __expf(-v1)));
                } else if (mode == M_SIGMUL) {
                    float2 h2 = *(const float2*)(hid + idx);
                    res = make_float2(rna_tf32(h2.x / (1.f + __expf(-v0))),
                                      rna_tf32(h2.y / (1.f + __expf(-v1))));
                } else { // M_FINAL
                    float2 u2 = *(const float2*)(g_u   + idx);
                    float2 z2 = *(const float2*)(g_z   + idx);
                    float2 a2 = *(const float2*)(g_c   + idx);
                    float2 p2 = *(const float2*)(g_php + idx);
                    float2 h2 = *(const float2*)(hid   + idx);
                    float t0 = tanhf(u2.x + v0), t1 = tanhf(u2.y + v1);
                    res = make_float2((1.f - z2.x) * t0 + z2.x * h2.x + a2.x * p2.x,
                                      (1.f - z2.y) * t1 + z2.y * h2.y + a2.y * p2.y);
                }
                *(float2*)(out + idx) = res;
            }
        }
    }
}

// ---------------- row softmax over g_c in place ----------------
__global__ __launch_bounds__(256)
void softmax_kernel()
{
    const int row = blockIdx.x;
    float* p = g_c + (size_t)row * HID;
    const int tid = threadIdx.x;

    float4 v = reinterpret_cast<float4*>(p)[tid];
    float m = fmaxf(fmaxf(v.x, v.y), fmaxf(v.z, v.w));
#pragma unroll
    for (int o = 16; o; o >>= 1) m = fmaxf(m, __shfl_xor_sync(~0u, m, o));

    __shared__ float smax[8];
    __shared__ float ssum[8];
    if ((tid & 31) == 0) smax[tid >> 5] = m;
    __syncthreads();
    float M = -1e30f;
#pragma unroll
    for (int i = 0; i < 8; i++) M = fmaxf(M, smax[i]);

    float e0 = expf(v.x - M), e1 = expf(v.y - M), e2 = expf(v.z - M), e3 = expf(v.w - M);
    float s = e0 + e1 + e2 + e3;
#pragma unroll
    for (int o = 16; o; o >>= 1) s += __shfl_xor_sync(~0u, s, o);
    if ((tid & 31) == 0) ssum[tid >> 5] = s;
    __syncthreads();
    float S = 0.f;
#pragma unroll
    for (int i = 0; i < 8; i++) S += ssum[i];
    float inv = 1.f / S;

    reinterpret_cast<float4*>(p)[tid] = make_float4(e0 * inv, e1 * inv, e2 * inv, e3 * inv);
}

// ---------------- launch ----------------
extern "C" void kernel_launch(void* const* d_in, const int* in_sizes, int n_in,
                              void* d_out, int out_size)
{
    const float* x    = (const float*)d_in[0];
    const float* h    = (const float*)d_in[1];
    const float* wxr  = (const float*)d_in[2];
    const float* whr  = (const float*)d_in[3];
    const float* br   = (const float*)d_in[4];
    const float* wxz  = (const float*)d_in[5];
    const float* whz  = (const float*)d_in[6];
    const float* bz   = (const float*)d_in[7];
    const float* wxh  = (const float*)d_in[8];
    const float* whh  = (const float*)d_in[9];
    const float* bh   = (const float*)d_in[10];
    const float* wc   = (const float*)d_in[11];
    const float* bc   = (const float*)d_in[12];
    const float* what = (const float*)d_in[13];
    const float* bhat = (const float*)d_in[14];

    float *pre, *pc, *pphp, *prh, *pz, *pu;
    cudaGetSymbolAddress((void**)&pre,  g_pre);
    cudaGetSymbolAddress((void**)&pc,   g_c);
    cudaGetSymbolAddress((void**)&pphp, g_php);
    cudaGetSymbolAddress((void**)&prh,  g_rh);
    cudaGetSymbolAddress((void**)&pz,   g_z);
    cudaGetSymbolAddress((void**)&pu,   g_u);

    KParams P;
    P.hidden = h;
    P.g[0] = {pre + PX, pre + PWC,   pre + PH, pre + PWC + 1024,   bc,   pc,   2048, 2048, 64, 64, M_NONE};
    P.g[1] = {pre + PX, pre + PWHAT, pre + PH, pre + PWHAT + 1024, bhat, pphp, 2048, 2048, 64, 64, M_RELU};
    P.g[2] = {pre + PX, pre + PWXR,  pre + PH, pre + PWHR,         br,   prh,  1024, 1024, 64, 64, M_SIGMUL};
    P.g[3] = {pre + PX, pre + PWXZ,  pre + PH, pre + PWHZ,         bz,   pz,   1024, 1024, 64, 64, M_SIG};
    P.g[4] = {pre + PX, pre + PWXH,  nullptr,  nullptr,            bh,   pu,   1024, 1024, 64, 0,  M_NONE};
    P.g[5] = {prh,      pre + PWHH,  nullptr,  nullptr,            nullptr, (float*)d_out, 1024, 1024, 64, 0, M_FINAL};

    cudaFuncSetAttribute(rau_gemm, cudaFuncAttributeMaxDynamicSharedMemorySize, SMEM_BYTES);

    preround_kernel<<<1024, 256>>>(x, h, wc, what, wxr, whr, wxz, whz, wxh, whh);

    // 5 independent projections batched in one launch (blockIdx.z selects gate)
    rau_gemm<<<dim3(HID / BN, BATCH / BM, 5), 256, SMEM_BYTES>>>(P, 0);

    // a = softmax(c) in place
    softmax_kernel<<<BATCH, 256>>>();

    // h_t = (1-z)*tanh(u + rh@Whh.T) + z*h + a*php
    rau_gemm<<<dim3(HID / BN, BATCH / BM, 1), 256, SMEM_BYTES>>>(P, 5);
}

// round 4
// speedup vs baseline: 2.1806x; 1.2091x over previous
#include <cuda_runtime.h>
#include <cstdint>
#include <math.h>

#define BATCH 8192
#define HID   1024

// ---------------- scratch (allocation-free: __device__ globals) ----------------
__device__ float g_c  [(size_t)BATCH * HID];   // c_t -> softmax a_t (in place)
__device__ float g_php[(size_t)BATCH * HID];   // relu(combined @ What.T + bhat)
__device__ float g_rh [(size_t)BATCH * HID];   // round_tf32(sigmoid(r_pre) * hidden)
__device__ float g_z  [(size_t)BATCH * HID];   // sigmoid(z_pre)
__device__ float g_u  [(size_t)BATCH * HID];   // x @ Wxh.T + bias_h

// pre-rounded (tf32-rna) operands, packed into one buffer (element offsets)
#define PX    0
#define PH    8388608
#define PWC   16777216
#define PWHAT 18874368
#define PWXR  20971520
#define PWHR  22020096
#define PWXZ  23068672
#define PWHZ  24117248
#define PWXH  25165824
#define PWHH  26214400
#define PTOT  27262976
__device__ float g_pre[PTOT];

__device__ __forceinline__ float rna_tf32(float f) {
    uint32_t u;
    asm("cvt.rna.tf32.f32 %0, %1;" : "=r"(u) : "f"(f));
    return __uint_as_float(u);
}
__device__ __forceinline__ uint32_t smem_to_u32(const void* p) {
    uint32_t a;
    asm("{ .reg .u64 tmp; cvta.to.shared.u64 tmp, %1; cvt.u32.u64 %0, tmp; }"
        : "=r"(a) : "l"(p));
    return a;
}

// ---------------- geometry ----------------
#define BM 128
#define BN 128
#define BK 16
#define SK 20                        // 16 + 4 pad words -> conflict-free fragment LDS
#define A_ST_B  10240                // 128*20*4 bytes per A stage
#define B_ST_B  10240                // 128*20*4 bytes per B stage
#define OFF_B_B 40960                // after 4 A stages
#define SMEM_BYTES (OFF_B_B + 4 * B_ST_B)   // 81920 -> 2 CTAs/SM

enum { M_NONE = 0, M_RELU = 1, M_SIG = 2, M_SIGMUL = 3, M_FINAL = 4 };

struct GateCfg {
    const float* A1; const float* W1;
    const float* A2; const float* W2;
    const float* bias; float* out;
    int ld1, ld2, n1, n2, mode;      // n1/n2 = #K16 chunks per phase
};
struct KParams { GateCfg g[6]; const float* hidden; };

// ---------------- pre-rounding pass (fp32 -> tf32-rna) ----------------
__global__ __launch_bounds__(256)
void preround_kernel(const float* x, const float* h, const float* wc, const float* what,
                     const float* wxr, const float* whr, const float* wxz, const float* whz,
                     const float* wxh, const float* whh)
{
    const int tid = blockIdx.x * blockDim.x + threadIdx.x;
    const int nt  = gridDim.x * blockDim.x;
    const float* srcs[10] = {x, h, wc, what, wxr, whr, wxz, whz, wxh, whh};
    float* dsts[10] = {g_pre + PX, g_pre + PH, g_pre + PWC, g_pre + PWHAT, g_pre + PWXR,
                       g_pre + PWHR, g_pre + PWXZ, g_pre + PWHZ, g_pre + PWXH, g_pre + PWHH};
    const int n4s[10] = {2097152, 2097152, 524288, 524288, 262144,
                         262144, 262144, 262144, 262144, 262144};
#pragma unroll 1
    for (int s = 0; s < 10; s++) {
        const float4* sp = (const float4*)srcs[s];
        float4*       dp = (float4*)dsts[s];
        const int n4 = n4s[s];
        for (int i = tid; i < n4; i += nt) {
            float4 v = sp[i];
            dp[i] = make_float4(rna_tf32(v.x), rna_tf32(v.y), rna_tf32(v.z), rna_tf32(v.w));
        }
    }
}

// ------- tf32 mma.sync GEMM, 128x128 CTA, 32x64 warp tile, 4-stage cp.async, 2 CTAs/SM -------
__global__ __launch_bounds__(256, 2)
void rau_gemm(KParams P, int gbase)
{
    extern __shared__ float smem[];
    const uint32_t su = smem_to_u32(smem);

    const GateCfg cfg = P.g[gbase + blockIdx.z];

    const int t = threadIdx.x;
    const int w = t >> 5, lane = t & 31;
    const int g = lane >> 2, tig = lane & 3;
    const int wm = w >> 1, wn = w & 1;        // 4x2 warp grid, 32x64 warp tile
    const int bm = blockIdx.y * BM;
    const int bn = blockIdx.x * BN;
    const int n1 = cfg.n1;
    const int n  = n1 + cfg.n2;

    // Per-thread load slots: 2 x 16B A, 2 x 16B B per chunk.
    uint32_t baseA[2], offA[2];
    uint32_t baseB[2], oW1[2], oW2[2];
#pragma unroll
    for (int j = 0; j < 2; j++) {
        int idx = j * 256 + t, row = idx >> 2, cg = idx & 3;
        baseA[j] = (uint32_t)(row * 80 + cg * 16);
        offA[j]  = (uint32_t)((bm + row) * HID + cg * 4);
        baseB[j] = (uint32_t)(OFF_B_B + row * 80 + cg * 16);
        oW1[j]   = (uint32_t)((bn + row) * cfg.ld1 + cg * 4);
        oW2[j]   = (uint32_t)((bn + row) * cfg.ld2 + cg * 4);
    }

    auto load_chunk = [&](int c, int st) {
        const bool p1 = (c < n1);
        const uint32_t kof = (uint32_t)(p1 ? c : c - n1) * 16u;
        const float* Ap = p1 ? cfg.A1 : cfg.A2;
        const float* Wp = p1 ? cfg.W1 : cfg.W2;
#pragma unroll
        for (int j = 0; j < 2; j++) {
            const float* s = Ap + offA[j] + kof;
            asm volatile("cp.async.cg.shared.global [%0], [%1], 16;\n"
                         :: "r"(su + st * A_ST_B + baseA[j]), "l"(s));
        }
#pragma unroll
        for (int j = 0; j < 2; j++) {
            const float* s = Wp + (p1 ? oW1[j] : oW2[j]) + kof;
            asm volatile("cp.async.cg.shared.global [%0], [%1], 16;\n"
                         :: "r"(su + st * B_ST_B + baseB[j]), "l"(s));
        }
    };

    float acc[2][8][4];
#pragma unroll
    for (int i = 0; i < 2; i++)
#pragma unroll
        for (int j = 0; j < 8; j++)
#pragma unroll
            for (int q = 0; q < 4; q++) acc[i][j][q] = 0.f;

    load_chunk(0, 0);
    asm volatile("cp.async.commit_group;\n" ::: "memory");
    load_chunk(1, 1);
    asm volatile("cp.async.commit_group;\n" ::: "memory");

#pragma unroll 1
    for (int i = 0; i < n; i++) {
        asm volatile("cp.async.wait_group 1;\n" ::: "memory");
        __syncthreads();
        if (i + 2 < n) load_chunk(i + 2, (i + 2) & 3);
        asm volatile("cp.async.commit_group;\n" ::: "memory");

        const int st = i & 3;
        const uint32_t* Asu = (const uint32_t*)((const char*)smem + st * A_ST_B);
        const uint32_t* Bsu = (const uint32_t*)((const char*)smem + OFF_B_B + st * B_ST_B);

#pragma unroll
        for (int kk = 0; kk < 2; kk++) {
            uint32_t af[2][4];
#pragma unroll
            for (int ii = 0; ii < 2; ii++) {
                int r0 = wm * 32 + ii * 16 + g;
                af[ii][0] = Asu[ r0      * SK + kk * 8 + tig    ];
                af[ii][1] = Asu[(r0 + 8) * SK + kk * 8 + tig    ];
                af[ii][2] = Asu[ r0      * SK + kk * 8 + tig + 4];
                af[ii][3] = Asu[(r0 + 8) * SK + kk * 8 + tig + 4];
            }
            uint32_t bf[8][2];
#pragma unroll
            for (int jj = 0; jj < 8; jj++) {
                int n0 = wn * 64 + jj * 8 + g;
                bf[jj][0] = Bsu[n0 * SK + kk * 8 + tig    ];
                bf[jj][1] = Bsu[n0 * SK + kk * 8 + tig + 4];
            }
#pragma unroll
            for (int ii = 0; ii < 2; ii++)
#pragma unroll
                for (int jj = 0; jj < 8; jj++) {
                    asm volatile(
                        "mma.sync.aligned.m16n8k8.row.col.f32.tf32.tf32.f32 "
                        "{%0,%1,%2,%3},{%4,%5,%6,%7},{%8,%9},{%0,%1,%2,%3};\n"
                        : "+f"(acc[ii][jj][0]), "+f"(acc[ii][jj][1]),
                          "+f"(acc[ii][jj][2]), "+f"(acc[ii][jj][3])
                        : "r"(af[ii][0]), "r"(af[ii][1]), "r"(af[ii][2]), "r"(af[ii][3]),
                          "r"(bf[jj][0]), "r"(bf[jj][1]));
                }
        }
    }

    // ---------------- fused epilogue ----------------
    const int mode = cfg.mode;
    float* out = cfg.out;
    const float* bias = cfg.bias;
    const float* hid = P.hidden;

#pragma unroll
    for (int ii = 0; ii < 2; ii++) {
#pragma unroll
        for (int jj = 0; jj < 8; jj++) {
            const int r0  = bm + wm * 32 + ii * 16 + g;
            const int col = bn + wn * 64 + jj * 8 + 2 * tig;
            float b0 = 0.f, b1 = 0.f;
            if (bias) { b0 = bias[col]; b1 = bias[col + 1]; }
#pragma unroll
            for (int hrow = 0; hrow < 2; hrow++) {
                const size_t idx = (size_t)(r0 + hrow * 8) * HID + col;
                float v0 = acc[ii][jj][hrow * 2    ] + b0;
                float v1 = acc[ii][jj][hrow * 2 + 1] + b1;
                float2 res;
                if (mode == M_NONE) {
                    res = make_float2(v0, v1);
                } else if (mode == M_RELU) {
                    res = make_float2(fmaxf(v0, 0.f), fmaxf(v1, 0.f));
                } else if (mode == M_SIG) {
                    res = make_float2(1.f / (1.f + __expf(-v0)),
                                      1.f / (1.f + __expf(-v1)));
                } else if (mode == M_SIGMUL) {
                    float2 h2 = *(const float2*)(hid + idx);
                    res = make_float2(rna_tf32(h2.x / (1.f + __expf(-v0))),
                                      rna_tf32(h2.y / (1.f + __expf(-v1))));
                } else { // M_FINAL
                    float2 u2 = *(const float2*)(g_u   + idx);
                    float2 z2 = *(const float2*)(g_z   + idx);
                    float2 a2 = *(const float2*)(g_c   + idx);
                    float2 p2 = *(const float2*)(g_php + idx);
                    float2 h2 = *(const float2*)(hid   + idx);
                    float t0 = tanhf(u2.x + v0), t1 = tanhf(u2.y + v1);
                    res = make_float2((1.f - z2.x) * t0 + z2.x * h2.x + a2.x * p2.x,
                                      (1.f - z2.y) * t1 + z2.y * h2.y + a2.y * p2.y);
                }
                *(float2*)(out + idx) = res;
            }
        }
    }
}

// ---------------- row softmax over g_c in place ----------------
__global__ __launch_bounds__(256)
void softmax_kernel()
{
    const int row = blockIdx.x;
    float* p = g_c + (size_t)row * HID;
    const int tid = threadIdx.x;

    float4 v = reinterpret_cast<float4*>(p)[tid];
    float m = fmaxf(fmaxf(v.x, v.y), fmaxf(v.z, v.w));
#pragma unroll
    for (int o = 16; o; o >>= 1) m = fmaxf(m, __shfl_xor_sync(~0u, m, o));

    __shared__ float smax[8];
    __shared__ float ssum[8];
    if ((tid & 31) == 0) smax[tid >> 5] = m;
    __syncthreads();
    float M = -1e30f;
#pragma unroll
    for (int i = 0; i < 8; i++) M = fmaxf(M, smax[i]);

    float e0 = expf(v.x - M), e1 = expf(v.y - M), e2 = expf(v.z - M), e3 = expf(v.w - M);
    float s = e0 + e1 + e2 + e3;
#pragma unroll
    for (int o = 16; o; o >>= 1) s += __shfl_xor_sync(~0u, s, o);
    if ((tid & 31) == 0) ssum[tid >> 5] = s;
    __syncthreads();
    float S = 0.f;
#pragma unroll
    for (int i = 0; i < 8; i++) S += ssum[i];
    float inv = 1.f / S;

    reinterpret_cast<float4*>(p)[tid] = make_float4(e0 * inv, e1 * inv, e2 * inv, e3 * inv);
}

// ---------------- launch ----------------
extern "C" void kernel_launch(void* const* d_in, const int* in_sizes, int n_in,
                              void* d_out, int out_size)
{
    const float* x    = (const float*)d_in[0];
    const float* h    = (const float*)d_in[1];
    const float* wxr  = (const float*)d_in[2];
    const float* whr  = (const float*)d_in[3];
    const float* br   = (const float*)d_in[4];
    const float* wxz  = (const float*)d_in[5];
    const float* whz  = (const float*)d_in[6];
    const float* bz   = (const float*)d_in[7];
    const float* wxh  = (const float*)d_in[8];
    const float* whh  = (const float*)d_in[9];
    const float* bh   = (const float*)d_in[10];
    const float* wc   = (const float*)d_in[11];
    const float* bc   = (const float*)d_in[12];
    const float* what = (const float*)d_in[13];
    const float* bhat = (const float*)d_in[14];

    float *pre, *pc, *pphp, *prh, *pz, *pu;
    cudaGetSymbolAddress((void**)&pre,  g_pre);
    cudaGetSymbolAddress((void**)&pc,   g_c);
    cudaGetSymbolAddress((void**)&pphp, g_php);
    cudaGetSymbolAddress((void**)&prh,  g_rh);
    cudaGetSymbolAddress((void**)&pz,   g_z);
    cudaGetSymbolAddress((void**)&pu,   g_u);

    KParams P;
    P.hidden = h;
    P.g[0] = {pre + PX, pre + PWC,   pre + PH, pre + PWC + 1024,   bc,   pc,   2048, 2048, 64, 64, M_NONE};
    P.g[1] = {pre + PX, pre + PWHAT, pre + PH, pre + PWHAT + 1024, bhat, pphp, 2048, 2048, 64, 64, M_RELU};
    P.g[2] = {pre + PX, pre + PWXR,  pre + PH, pre + PWHR,         br,   prh,  1024, 1024, 64, 64, M_SIGMUL};
    P.g[3] = {pre + PX, pre + PWXZ,  pre + PH, pre + PWHZ,         bz,   pz,   1024, 1024, 64, 64, M_SIG};
    P.g[4] = {pre + PX, pre + PWXH,  nullptr,  nullptr,            bh,   pu,   1024, 1024, 64, 0,  M_NONE};
    P.g[5] = {prh,      pre + PWHH,  nullptr,  nullptr,            nullptr, (float*)d_out, 1024, 1024, 64, 0, M_FINAL};

    cudaFuncSetAttribute(rau_gemm, cudaFuncAttributeMaxDynamicSharedMemorySize, SMEM_BYTES);

    preround_kernel<<<1024, 256>>>(x, h, wc, what, wxr, whr, wxz, whz, wxh, whh);

    // 5 independent projections batched in one launch (blockIdx.z selects gate)
    rau_gemm<<<dim3(HID / BN, BATCH / BM, 5), 256, SMEM_BYTES>>>(P, 0);

    // a = softmax(c) in place
    softmax_kernel<<<BATCH, 256>>>();

    // h_t = (1-z)*tanh(u + rh@Whh.T) + z*h + a*php
    rau_gemm<<<dim3(HID / BN, BATCH / BM, 1), 256, SMEM_BYTES>>>(P, 5);
}

// round 6
// speedup vs baseline: 2.3870x; 1.0946x over previous
#include <cuda_runtime.h>
#include <cstdint>
#include <math.h>

#define BATCH 8192
#define HID   1024

// ---------------- scratch (allocation-free: __device__ globals) ----------------
__device__ float g_c  [(size_t)BATCH * HID];   // c_t -> softmax a_t (in place)
__device__ float g_php[(size_t)BATCH * HID];   // relu(combined @ What.T + bhat)
__device__ float g_rh [(size_t)BATCH * HID];   // round_tf32(sigmoid(r_pre) * hidden)
__device__ float g_z  [(size_t)BATCH * HID];   // sigmoid(z_pre)
__device__ float g_u  [(size_t)BATCH * HID];   // x @ Wxh.T + bias_h

// pre-rounded (tf32-rna) operands, packed into one buffer (element offsets)
#define PX    0
#define PH    8388608
#define PWC   16777216
#define PWHAT 18874368
#define PWXR  20971520
#define PWHR  22020096
#define PWXZ  23068672
#define PWHZ  24117248
#define PWXH  25165824
#define PWHH  26214400
#define PTOT  27262976
__device__ float g_pre[PTOT];

__device__ __forceinline__ float rna_tf32(float f) {
    uint32_t u;
    asm("cvt.rna.tf32.f32 %0, %1;" : "=r"(u) : "f"(f));
    return __uint_as_float(u);
}
__device__ __forceinline__ uint32_t smem_to_u32(const void* p) {
    uint32_t a;
    asm("{ .reg .u64 tmp; cvta.to.shared.u64 tmp, %1; cvt.u32.u64 %0, tmp; }"
        : "=r"(a) : "l"(p));
    return a;
}

// ---------------- geometry ----------------
#define BM 128
#define BN 128
#define BK 16
#define SK 20                        // 16 + 4 pad words -> conflict-free LDSM (stride 80B)
#define A_ST_B  10240                // 128*20*4 bytes per A stage
#define B_ST_B  10240
#define OFF_B_B 40960                // after 4 A stages
#define SMEM_BYTES (OFF_B_B + 4 * B_ST_B)   // 81920 -> 2 CTAs/SM

enum { M_NONE = 0, M_RELU = 1, M_SIG = 2, M_SIGMUL = 3, M_FINAL = 4 };

struct GateCfg {
    const float* A1; const float* W1;
    const float* A2; const float* W2;
    const float* bias; float* out;
    int ld1, ld2, n1, n2, mode;      // n1/n2 = #K16 chunks per phase
};
struct KParams { GateCfg g[6]; const float* hidden; };

// ---------------- pre-rounding pass (fp32 -> tf32-rna) ----------------
__global__ __launch_bounds__(256)
void preround_kernel(const float* x, const float* h, const float* wc, const float* what,
                     const float* wxr, const float* whr, const float* wxz, const float* whz,
                     const float* wxh, const float* whh)
{
    const int tid = blockIdx.x * blockDim.x + threadIdx.x;
    const int nt  = gridDim.x * blockDim.x;
    const float* srcs[10] = {x, h, wc, what, wxr, whr, wxz, whz, wxh, whh};
    float* dsts[10] = {g_pre + PX, g_pre + PH, g_pre + PWC, g_pre + PWHAT, g_pre + PWXR,
                       g_pre + PWHR, g_pre + PWXZ, g_pre + PWHZ, g_pre + PWXH, g_pre + PWHH};
    const int n4s[10] = {2097152, 2097152, 524288, 524288, 262144,
                         262144, 262144, 262144, 262144, 262144};
#pragma unroll 1
    for (int s = 0; s < 10; s++) {
        const float4* sp = (const float4*)srcs[s];
        float4*       dp = (float4*)dsts[s];
        const int n4 = n4s[s];
        for (int i = tid; i < n4; i += nt) {
            float4 v = sp[i];
            dp[i] = make_float4(rna_tf32(v.x), rna_tf32(v.y), rna_tf32(v.z), rna_tf32(v.w));
        }
    }
}

// ------- tf32 mma.sync GEMM, 128x128 CTA, 32x64 warp tile, ldmatrix frags, 2 CTAs/SM -------
__global__ __launch_bounds__(256, 2)
void rau_gemm(KParams P, int gbase)
{
    extern __shared__ float smem[];
    const uint32_t su = smem_to_u32(smem);

    const GateCfg cfg = P.g[gbase + blockIdx.z];

    const int t = threadIdx.x;
    const int w = t >> 5, lane = t & 31;
    const int g = lane >> 2, tig = lane & 3;
    const int wm = w >> 1, wn = w & 1;        // 4x2 warp grid, 32x64 warp tile
    const int bm = blockIdx.y * BM;
    const int bn = blockIdx.x * BN;
    const int n1 = cfg.n1;
    const int n  = n1 + cfg.n2;

    // Per-thread cp.async slots: 2 x 16B A, 2 x 16B B per chunk.
    uint32_t baseA[2], offA[2];
    uint32_t baseB[2], oW1[2], oW2[2];
#pragma unroll
    for (int j = 0; j < 2; j++) {
        int idx = j * 256 + t, row = idx >> 2, cg = idx & 3;
        baseA[j] = (uint32_t)(row * 80 + cg * 16);
        offA[j]  = (uint32_t)((bm + row) * HID + cg * 4);
        baseB[j] = (uint32_t)(OFF_B_B + row * 80 + cg * 16);
        oW1[j]   = (uint32_t)((bn + row) * cfg.ld1 + cg * 4);
        oW2[j]   = (uint32_t)((bn + row) * cfg.ld2 + cg * 4);
    }

    // ldmatrix per-lane row addresses.
    // A x4 tiles (a0..a3) = (rows+0,c+0),(rows+8,c+0),(rows+0,c+4),(rows+8,c+4)
    const uint32_t aAddr = su +
        (uint32_t)(((wm * 32 + ((lane >> 3) & 1) * 8 + (lane & 7)) * SK +
                    ((lane >> 4) & 1) * 4) * 4);
    // B x4 tiles (b[jj][0], b[jj][1], b[jj+1][0], b[jj+1][1]) = col+4 on bit0, rows+8 on bit1
    const uint32_t bAddr = su + OFF_B_B +
        (uint32_t)(((wn * 64 + ((lane >> 4) & 1) * 8 + (lane & 7)) * SK +
                    ((lane >> 3) & 1) * 4) * 4);

    auto load_chunk = [&](int c, int st) {
        const bool p1 = (c < n1);
        const uint32_t kof = (uint32_t)(p1 ? c : c - n1) * 16u;
        const float* Ap = p1 ? cfg.A1 : cfg.A2;
        const float* Wp = p1 ? cfg.W1 : cfg.W2;
#pragma unroll
        for (int j = 0; j < 2; j++) {
            const float* s = Ap + offA[j] + kof;
            asm volatile("cp.async.cg.shared.global [%0], [%1], 16;\n"
                         :: "r"(su + st * A_ST_B + baseA[j]), "l"(s));
        }
#pragma unroll
        for (int j = 0; j < 2; j++) {
            const float* s = Wp + (p1 ? oW1[j] : oW2[j]) + kof;
            asm volatile("cp.async.cg.shared.global [%0], [%1], 16;\n"
                         :: "r"(su + st * B_ST_B + baseB[j]), "l"(s));
        }
    };

    float acc[2][8][4];
#pragma unroll
    for (int i = 0; i < 2; i++)
#pragma unroll
        for (int j = 0; j < 8; j++)
#pragma unroll
            for (int q = 0; q < 4; q++) acc[i][j][q] = 0.f;

    load_chunk(0, 0);
    asm volatile("cp.async.commit_group;\n" ::: "memory");
    load_chunk(1, 1);
    asm volatile("cp.async.commit_group;\n" ::: "memory");
    load_chunk(2, 2);
    asm volatile("cp.async.commit_group;\n" ::: "memory");

#pragma unroll 1
    for (int i = 0; i < n; i++) {
        asm volatile("cp.async.wait_group 2;\n" ::: "memory");
        __syncthreads();
        if (i + 3 < n) load_chunk(i + 3, (i + 3) & 3);
        asm volatile("cp.async.commit_group;\n" ::: "memory");

        const int st = i & 3;
        const uint32_t aS = aAddr + st * A_ST_B;
        const uint32_t bS = bAddr + st * B_ST_B;

#pragma unroll
        for (int kk = 0; kk < 2; kk++) {
            uint32_t af[2][4];
#pragma unroll
            for (int ii = 0; ii < 2; ii++) {
                asm volatile("ldmatrix.sync.aligned.m8n8.x4.shared.b16 {%0,%1,%2,%3}, [%4];"
                             : "=r"(af[ii][0]), "=r"(af[ii][1]),
                               "=r"(af[ii][2]), "=r"(af[ii][3])
                             : "r"(aS + kk * 32 + ii * (16 * SK * 4)));
            }
            uint32_t bf[8][2];
#pragma unroll
            for (int jp = 0; jp < 4; jp++) {
                asm volatile("ldmatrix.sync.aligned.m8n8.x4.shared.b16 {%0,%1,%2,%3}, [%4];"
                             : "=r"(bf[jp * 2][0]),     "=r"(bf[jp * 2][1]),
                               "=r"(bf[jp * 2 + 1][0]), "=r"(bf[jp * 2 + 1][1])
                             : "r"(bS + kk * 32 + jp * (16 * SK * 4)));
            }
#pragma unroll
            for (int ii = 0; ii < 2; ii++)
#pragma unroll
                for (int jj = 0; jj < 8; jj++) {
                    asm volatile(
                        "mma.sync.aligned.m16n8k8.row.col.f32.tf32.tf32.f32 "
                        "{%0,%1,%2,%3},{%4,%5,%6,%7},{%8,%9},{%0,%1,%2,%3};\n"
                        : "+f"(acc[ii][jj][0]), "+f"(acc[ii][jj][1]),
                          "+f"(acc[ii][jj][2]), "+f"(acc[ii][jj][3])
                        : "r"(af[ii][0]), "r"(af[ii][1]), "r"(af[ii][2]), "r"(af[ii][3]),
                          "r"(bf[jj][0]), "r"(bf[jj][1]));
                }
        }
    }

    // ---------------- fused epilogue ----------------
    const int mode = cfg.mode;
    float* out = cfg.out;
    const float* bias = cfg.bias;
    const float* hid = P.hidden;

#pragma unroll
    for (int ii = 0; ii < 2; ii++) {
#pragma unroll
        for (int jj = 0; jj < 8; jj++) {
            const int r0  = bm + wm * 32 + ii * 16 + g;
            const int col = bn + wn * 64 + jj * 8 + 2 * tig;
            float b0 = 0.f, b1 = 0.f;
            if (bias) { b0 = bias[col]; b1 = bias[col + 1]; }
#pragma unroll
            for (int hrow = 0; hrow < 2; hrow++) {
                const size_t idx = (size_t)(r0 + hrow * 8) * HID + col;
                float v0 = acc[ii][jj][hrow * 2    ] + b0;
                float v1 = acc[ii][jj][hrow * 2 + 1] + b1;
                float2 res;
                if (mode == M_NONE) {
                    res = make_float2(v0, v1);
                } else if (mode == M_RELU) {
                    res = make_float2(fmaxf(v0, 0.f), fmaxf(v1, 0.f));
                } else if (mode == M_SIG) {
                    res = make_float2(1.f / (1.f + __expf(-v0)),
                                      1.f / (1.f + __expf(-v1)));
                } else if (mode == M_SIGMUL) {
                    float2 h2 = *(const float2*)(hid + idx);
                    res = make_float2(rna_tf32(h2.x / (1.f + __expf(-v0))),
                                      rna_tf32(h2.y / (1.f + __expf(-v1))));
                } else { // M_FINAL
                    float2 u2 = *(const float2*)(g_u   + idx);
                    float2 z2 = *(const float2*)(g_z   + idx);
                    float2 a2 = *(const float2*)(g_c   + idx);
                    float2 p2 = *(const float2*)(g_php + idx);
                    float2 h2 = *(const float2*)(hid   + idx);
                    float t0 = tanhf(u2.x + v0), t1 = tanhf(u2.y + v1);
                    res = make_float2((1.f - z2.x) * t0 + z2.x * h2.x + a2.x * p2.x,
                                      (1.f - z2.y) * t1 + z2.y * h2.y + a2.y * p2.y);
                }
                *(float2*)(out + idx) = res;
            }
        }
    }
}

// ---------------- row softmax over g_c in place ----------------
__global__ __launch_bounds__(256)
void softmax_kernel()
{
    const int row = blockIdx.x;
    float* p = g_c + (size_t)row * HID;
    const int tid = threadIdx.x;

    float4 v = reinterpret_cast<float4*>(p)[tid];
    float m = fmaxf(fmaxf(v.x, v.y), fmaxf(v.z, v.w));
#pragma unroll
    for (int o = 16; o; o >>= 1) m = fmaxf(m, __shfl_xor_sync(~0u, m, o));

    __shared__ float smax[8];
    __shared__ float ssum[8];
    if ((tid & 31) == 0) smax[tid >> 5] = m;
    __syncthreads();
    float M = -1e30f;
#pragma unroll
    for (int i = 0; i < 8; i++) M = fmaxf(M, smax[i]);

    float e0 = expf(v.x - M), e1 = expf(v.y - M), e2 = expf(v.z - M), e3 = expf(v.w - M);
    float s = e0 + e1 + e2 + e3;
#pragma unroll
    for (int o = 16; o; o >>= 1) s += __shfl_xor_sync(~0u, s, o);
    if ((tid & 31) == 0) ssum[tid >> 5] = s;
    __syncthreads();
    float S = 0.f;
#pragma unroll
    for (int i = 0; i < 8; i++) S += ssum[i];
    float inv = 1.f / S;

    reinterpret_cast<float4*>(p)[tid] = make_float4(e0 * inv, e1 * inv, e2 * inv, e3 * inv);
}

// ---------------- launch ----------------
extern "C" void kernel_launch(void* const* d_in, const int* in_sizes, int n_in,
                              void* d_out, int out_size)
{
    const float* x    = (const float*)d_in[0];
    const float* h    = (const float*)d_in[1];
    const float* wxr  = (const float*)d_in[2];
    const float* whr  = (const float*)d_in[3];
    const float* br   = (const float*)d_in[4];
    const float* wxz  = (const float*)d_in[5];
    const float* whz  = (const float*)d_in[6];
    const float* bz   = (const float*)d_in[7];
    const float* wxh  = (const float*)d_in[8];
    const float* whh  = (const float*)d_in[9];
    const float* bh   = (const float*)d_in[10];
    const float* wc   = (const float*)d_in[11];
    const float* bc   = (const float*)d_in[12];
    const float* what = (const float*)d_in[13];
    const float* bhat = (const float*)d_in[14];

    float *pre, *pc, *pphp, *prh, *pz, *pu;
    cudaGetSymbolAddress((void**)&pre,  g_pre);
    cudaGetSymbolAddress((void**)&pc,   g_c);
    cudaGetSymbolAddress((void**)&pphp, g_php);
    cudaGetSymbolAddress((void**)&prh,  g_rh);
    cudaGetSymbolAddress((void**)&pz,   g_z);
    cudaGetSymbolAddress((void**)&pu,   g_u);

    KParams P;
    P.hidden = h;
    P.g[0] = {pre + PX, pre + PWC,   pre + PH, pre + PWC + 1024,   bc,   pc,   2048, 2048, 64, 64, M_NONE};
    P.g[1] = {pre + PX, pre + PWHAT, pre + PH, pre + PWHAT + 1024, bhat, pphp, 2048, 2048, 64, 64, M_RELU};
    P.g[2] = {pre + PX, pre + PWXR,  pre + PH, pre + PWHR,         br,   prh,  1024, 1024, 64, 64, M_SIGMUL};
    P.g[3] = {pre + PX, pre + PWXZ,  pre + PH, pre + PWHZ,         bz,   pz,   1024, 1024, 64, 64, M_SIG};
    P.g[4] = {pre + PX, pre + PWXH,  nullptr,  nullptr,            bh,   pu,   1024, 1024, 64, 0,  M_NONE};
    P.g[5] = {prh,      pre + PWHH,  nullptr,  nullptr,            nullptr, (float*)d_out, 1024, 1024, 64, 0, M_FINAL};

    cudaFuncSetAttribute(rau_gemm, cudaFuncAttributeMaxDynamicSharedMemorySize, SMEM_BYTES);

    preround_kernel<<<1024, 256>>>(x, h, wc, what, wxr, whr, wxz, whz, wxh, whh);

    // 5 independent projections batched in one launch (blockIdx.z selects gate)
    rau_gemm<<<dim3(HID / BN, BATCH / BM, 5), 256, SMEM_BYTES>>>(P, 0);

    // a = softmax(c) in place
    softmax_kernel<<<BATCH, 256>>>();

    // h_t = (1-z)*tanh(u + rh@Whh.T) + z*h + a*php
    rau_gemm<<<dim3(HID / BN, BATCH / BM, 1), 256, SMEM_BYTES>>>(P, 5);
}